// round 3
// baseline (speedup 1.0000x reference)
#include <cuda_runtime.h>
#include <math.h>

#define BATCH 32
#define SEQ   1024
#define DIN   128
#define HID   256
#define G4    1024   // 4*H
#define H2    512    // 2*H

// ---------------- scratch (device globals; no allocation allowed) ----------------
__device__ float  g_xpf[(size_t)BATCH * SEQ * G4];   // 128 MB
__device__ float  g_xpb[(size_t)BATCH * SEQ * G4];   // 128 MB
__device__ float  g_h0 [(size_t)BATCH * SEQ * H2];   // 64 MB
__device__ float  g_h1 [(size_t)BATCH * SEQ * H2];   // 64 MB
__device__ float  g_ctx[(size_t)BATCH * SEQ * H2];   // 64 MB
__device__ float4 g_wT [4 * HID * HID];              // 4 x 1MB interleaved-transposed w_hh
__device__ float  g_e  [BATCH * SEQ];

// ---------------- w_hh transpose+interleave: out[k*256+n] = {w[n][k], w[n+256][k], w[n+512][k], w[n+768][k]} ----
__global__ void prep_whh(const float* __restrict__ w, float4* __restrict__ out) {
    int idx = blockIdx.x * 256 + threadIdx.x;   // 65536 total
    int k = idx >> 8, n = idx & 255;
    out[idx] = make_float4(w[(n      ) * HID + k],
                           w[(n + 256) * HID + k],
                           w[(n + 512) * HID + k],
                           w[(n + 768) * HID + k]);
}

// ---------------- SGEMM: C[m*N+n] = bias[n] + sum_k A[m*K+k] * W[n*K+k] ----------------
// BM=BN=128, BK=8, 256 threads, 8x8 microtile. M%128==0, N%128==0, K%8==0.
__global__ void __launch_bounds__(256) sgemm_tn(const float* __restrict__ A,
                                               const float* __restrict__ W,
                                               const float* __restrict__ bias,
                                               float* __restrict__ C,
                                               int M, int N, int K) {
    __shared__ float As[8][128];
    __shared__ float Ws[8][128];
    int tid = threadIdx.x;
    int m0 = blockIdx.x * 128, n0 = blockIdx.y * 128;
    int la_m = tid >> 1;
    int la_k = (tid & 1) * 4;
    int tm0 = (tid >> 4) * 8;
    int tn0 = (tid & 15) * 8;

    float acc[8][8];
#pragma unroll
    for (int i = 0; i < 8; i++)
#pragma unroll
        for (int j = 0; j < 8; j++) acc[i][j] = 0.f;

    for (int k0 = 0; k0 < K; k0 += 8) {
        float4 av = *(const float4*)&A[(size_t)(m0 + la_m) * K + k0 + la_k];
        float4 wv = *(const float4*)&W[(size_t)(n0 + la_m) * K + k0 + la_k];
        __syncthreads();
        As[la_k + 0][la_m] = av.x; As[la_k + 1][la_m] = av.y;
        As[la_k + 2][la_m] = av.z; As[la_k + 3][la_m] = av.w;
        Ws[la_k + 0][la_m] = wv.x; Ws[la_k + 1][la_m] = wv.y;
        Ws[la_k + 2][la_m] = wv.z; Ws[la_k + 3][la_m] = wv.w;
        __syncthreads();
#pragma unroll
        for (int kk = 0; kk < 8; kk++) {
            float ra[8], rw[8];
            *(float4*)(ra)     = *(const float4*)&As[kk][tm0];
            *(float4*)(ra + 4) = *(const float4*)&As[kk][tm0 + 4];
            *(float4*)(rw)     = *(const float4*)&Ws[kk][tn0];
            *(float4*)(rw + 4) = *(const float4*)&Ws[kk][tn0 + 4];
#pragma unroll
            for (int i = 0; i < 8; i++)
#pragma unroll
                for (int j = 0; j < 8; j++) acc[i][j] += ra[i] * rw[j];
        }
    }

    float bj[8];
#pragma unroll
    for (int j = 0; j < 8; j++) bj[j] = bias[n0 + tn0 + j];
#pragma unroll
    for (int i = 0; i < 8; i++) {
        float* cr = &C[(size_t)(m0 + tm0 + i) * N + n0 + tn0];
#pragma unroll
        for (int j = 0; j < 8; j++) cr[j] = acc[i][j] + bj[j];
    }
}

// ---------------- LSTM scan: one block per (dir, batch), 256 threads ----------------
// xp layout [B][S][4H] (natural time order; bw reads reversed indices).
// wT: interleaved-transposed [dir][k*256+n] float4. out: [B][S][512], fw->cols [0,256), bw->[256,512).
__global__ void __launch_bounds__(256) lstm_scan(const float* __restrict__ xpf,
                                                 const float* __restrict__ xpb,
                                                 const float4* __restrict__ wT,
                                                 float* __restrict__ out) {
    int d = blockIdx.x;   // 0 = fw, 1 = bw
    int b = blockIdx.y;
    const float*  xp = d ? xpb : xpf;
    const float4* w  = wT + (size_t)d * HID * HID;
    int n = threadIdx.x;

    __shared__ float sh[HID];
    sh[n] = 0.f;
    float c = 0.f;
    __syncthreads();

    for (int t = 0; t < SEQ; t++) {
        int s = d ? (SEQ - 1 - t) : t;
        const float* xr = xp + ((size_t)b * SEQ + s) * G4;
        float ai = xr[n];
        float af = xr[n + 256];
        float ag = xr[n + 512];
        float ao = xr[n + 768];
#pragma unroll 4
        for (int k = 0; k < HID; k += 4) {
            float4 hv = *(const float4*)&sh[k];
            float4 w0 = w[(k + 0) * HID + n];
            float4 w1 = w[(k + 1) * HID + n];
            float4 w2 = w[(k + 2) * HID + n];
            float4 w3 = w[(k + 3) * HID + n];
            ai += hv.x * w0.x + hv.y * w1.x + hv.z * w2.x + hv.w * w3.x;
            af += hv.x * w0.y + hv.y * w1.y + hv.z * w2.y + hv.w * w3.y;
            ag += hv.x * w0.z + hv.y * w1.z + hv.z * w2.z + hv.w * w3.z;
            ao += hv.x * w0.w + hv.y * w1.w + hv.z * w2.w + hv.w * w3.w;
        }
        float ig = 1.f / (1.f + expf(-ai));
        float fg = 1.f / (1.f + expf(-af));
        float gg = tanhf(ag);
        float og = 1.f / (1.f + expf(-ao));
        c = fg * c + ig * gg;
        float h = og * tanhf(c);
        __syncthreads();           // everyone done reading old sh
        sh[n] = h;
        out[((size_t)b * SEQ + s) * H2 + d * HID + n] = h;
        __syncthreads();           // new sh visible
    }
}

// ---------------- attention scores -> e = exp(s - max_t s) ----------------
__global__ void __launch_bounds__(256) attn_scores(const float* __restrict__ h,
                                                   const float* __restrict__ attn_w,
                                                   const float* __restrict__ attn_b,
                                                   float* __restrict__ e_out) {
    int b = blockIdx.x;
    int tid = threadIdx.x;
    __shared__ float sc[SEQ];
    __shared__ float red[256];
    __shared__ float wsh[H2];
    wsh[tid]       = attn_w[tid];
    wsh[tid + 256] = attn_w[tid + 256];
    __syncthreads();
    float ab = attn_b[0];
    float mx = -1e30f;
    for (int t = tid; t < SEQ; t += 256) {
        const float* hr = h + ((size_t)b * SEQ + t) * H2;
        float acc = 0.f;
#pragma unroll 4
        for (int cch = 0; cch < H2; cch += 4) {
            float4 hv = *(const float4*)&hr[cch];
            acc += hv.x * wsh[cch] + hv.y * wsh[cch + 1] + hv.z * wsh[cch + 2] + hv.w * wsh[cch + 3];
        }
        acc += ab;
        sc[t] = acc;
        mx = fmaxf(mx, acc);
    }
    red[tid] = mx;
    __syncthreads();
    for (int s = 128; s > 0; s >>= 1) {
        if (tid < s) red[tid] = fmaxf(red[tid], red[tid + s]);
        __syncthreads();
    }
    mx = red[0];
    for (int t = tid; t < SEQ; t += 256)
        e_out[b * SEQ + t] = expf(sc[t] - mx);
}

// ---------------- running-softmax context: ctx[b][t][ch] = cumsum(e*h)/cumsum(e) ----------------
__global__ void __launch_bounds__(512) ctx_kernel(const float* __restrict__ h,
                                                  const float* __restrict__ e,
                                                  float* __restrict__ ctx) {
    int b = blockIdx.x;
    int ch = threadIdx.x;
    const float* eb = e + b * SEQ;
    float num = 0.f, den = 0.f;
    for (int t = 0; t < SEQ; t++) {
        float et = eb[t];
        den += et;
        size_t off = ((size_t)b * SEQ + t) * H2 + ch;
        num += et * h[off];
        ctx[off] = num / den;
    }
}

// ---------------- launch ----------------
extern "C" void kernel_launch(void* const* d_in, const int* in_sizes, int n_in,
                              void* d_out, int out_size) {
    const float* x        = (const float*)d_in[0];
    const float* w_ih_l0f = (const float*)d_in[1];
    const float* w_hh_l0f = (const float*)d_in[2];
    const float* b_l0f    = (const float*)d_in[3];
    const float* w_ih_l0b = (const float*)d_in[4];
    const float* w_hh_l0b = (const float*)d_in[5];
    const float* b_l0b    = (const float*)d_in[6];
    const float* w_ih_l1f = (const float*)d_in[7];
    const float* w_hh_l1f = (const float*)d_in[8];
    const float* b_l1f    = (const float*)d_in[9];
    const float* w_ih_l1b = (const float*)d_in[10];
    const float* w_hh_l1b = (const float*)d_in[11];
    const float* b_l1b    = (const float*)d_in[12];
    const float* attn_w   = (const float*)d_in[13];
    const float* attn_b   = (const float*)d_in[14];
    const float* head_w   = (const float*)d_in[15];
    const float* head_b   = (const float*)d_in[16];
    float* out = (float*)d_out;

    float *xpf, *xpb, *h0, *h1, *ctx, *ev;
    float4* wT;
    cudaGetSymbolAddress((void**)&xpf, g_xpf);
    cudaGetSymbolAddress((void**)&xpb, g_xpb);
    cudaGetSymbolAddress((void**)&h0,  g_h0);
    cudaGetSymbolAddress((void**)&h1,  g_h1);
    cudaGetSymbolAddress((void**)&ctx, g_ctx);
    cudaGetSymbolAddress((void**)&wT,  g_wT);
    cudaGetSymbolAddress((void**)&ev,  g_e);

    const int M = BATCH * SEQ;   // 32768

    // w_hh interleaved transposes: [0]=l0f, [1]=l0b, [2]=l1f, [3]=l1b
    prep_whh<<<256, 256>>>(w_hh_l0f, wT + 0 * HID * HID);
    prep_whh<<<256, 256>>>(w_hh_l0b, wT + 1 * HID * HID);
    prep_whh<<<256, 256>>>(w_hh_l1f, wT + 2 * HID * HID);
    prep_whh<<<256, 256>>>(w_hh_l1b, wT + 3 * HID * HID);

    // layer 0 input projections: [32768,128] x [1024,128]^T -> [32768,1024]
    {
        dim3 grid(M / 128, G4 / 128);
        sgemm_tn<<<grid, 256>>>(x, w_ih_l0f, b_l0f, xpf, M, G4, DIN);
        sgemm_tn<<<grid, 256>>>(x, w_ih_l0b, b_l0b, xpb, M, G4, DIN);
    }
    // layer 0 scan
    {
        dim3 grid(2, BATCH);
        lstm_scan<<<grid, 256>>>(xpf, xpb, wT, h0);
    }
    // layer 1 input projections: K=512
    {
        dim3 grid(M / 128, G4 / 128);
        sgemm_tn<<<grid, 256>>>(h0, w_ih_l1f, b_l1f, xpf, M, G4, H2);
        sgemm_tn<<<grid, 256>>>(h0, w_ih_l1b, b_l1b, xpb, M, G4, H2);
    }
    // layer 1 scan
    {
        dim3 grid(2, BATCH);
        lstm_scan<<<grid, 256>>>(xpf, xpb, wT + 2 * HID * HID, h1);
    }
    // attention + running softmax context
    attn_scores<<<BATCH, 256>>>(h1, attn_w, attn_b, ev);
    ctx_kernel<<<BATCH, 512>>>(h1, ev, ctx);

    // head: [32768,512] x [128,512]^T + head_b -> out [32768,128]
    {
        dim3 grid(M / 128, DIN / 128);
        sgemm_tn<<<grid, 256>>>(ctx, head_w, head_b, out, M, DIN, H2);
    }
}

// round 4
// speedup vs baseline: 1.5292x; 1.5292x over previous
#include <cuda_runtime.h>
#include <math.h>
#include <stdint.h>

#define BATCH 32
#define SEQ   1024
#define DIN   128
#define HID   256
#define G4    1024   // 4*H
#define H2    512    // 2*H

// ---------------- scratch (device globals; no allocation allowed) ----------------
__device__ float  g_xpf[(size_t)BATCH * SEQ * G4];   // 128 MB
__device__ float  g_xpb[(size_t)BATCH * SEQ * G4];   // 128 MB
__device__ float  g_h0 [(size_t)BATCH * SEQ * H2];   // 64 MB
__device__ float  g_h1 [(size_t)BATCH * SEQ * H2];   // 64 MB
__device__ float  g_ctx[(size_t)BATCH * SEQ * H2];   // 64 MB
__device__ float  g_e  [BATCH * SEQ];

// ---------------- f32x2 packed-FMA helpers (sm_103a) ----------------
__device__ __forceinline__ unsigned long long ffma2(unsigned long long a,
                                                    unsigned long long b,
                                                    unsigned long long c) {
    unsigned long long d;
    asm("fma.rn.f32x2 %0, %1, %2, %3;" : "=l"(d) : "l"(a), "l"(b), "l"(c));
    return d;
}
__device__ __forceinline__ unsigned long long pack2(float x, float y) {
    unsigned long long r;
    asm("mov.b64 %0, {%1, %2};" : "=l"(r) : "f"(x), "f"(y));
    return r;
}
__device__ __forceinline__ void unpack2(unsigned long long v, float& x, float& y) {
    asm("mov.b64 {%0, %1}, %2;" : "=f"(x), "=f"(y) : "l"(v));
}

__device__ __forceinline__ float sigm_fast(float x) {
    return 1.f / (1.f + __expf(-x));
}
__device__ __forceinline__ float tanh_fast(float x) {
    return 2.f / (1.f + __expf(-2.f * x)) - 1.f;
}

// ---------------- SGEMM: C[m*N+n] = bias[n] + sum_k A[m*K+k] * W[n*K+k] ----------------
// BM=BN=128, BK=8, 256 threads, 8x8 microtile with f32x2 packed FMA over n-pairs.
__global__ void __launch_bounds__(256) sgemm_tn(const float* __restrict__ A,
                                               const float* __restrict__ W,
                                               const float* __restrict__ bias,
                                               float* __restrict__ C,
                                               int M, int N, int K) {
    __shared__ float As[8][128];
    __shared__ float Ws[8][128];
    int tid = threadIdx.x;
    int m0 = blockIdx.x * 128, n0 = blockIdx.y * 128;
    int la_m = tid >> 1;
    int la_k = (tid & 1) * 4;
    int tm0 = (tid >> 4) * 8;
    int tn0 = (tid & 15) * 8;

    unsigned long long acc2[8][4];
#pragma unroll
    for (int i = 0; i < 8; i++)
#pragma unroll
        for (int j = 0; j < 4; j++) acc2[i][j] = 0ull;

    for (int k0 = 0; k0 < K; k0 += 8) {
        float4 av = *(const float4*)&A[(size_t)(m0 + la_m) * K + k0 + la_k];
        float4 wv = *(const float4*)&W[(size_t)(n0 + la_m) * K + k0 + la_k];
        __syncthreads();
        As[la_k + 0][la_m] = av.x; As[la_k + 1][la_m] = av.y;
        As[la_k + 2][la_m] = av.z; As[la_k + 3][la_m] = av.w;
        Ws[la_k + 0][la_m] = wv.x; Ws[la_k + 1][la_m] = wv.y;
        Ws[la_k + 2][la_m] = wv.z; Ws[la_k + 3][la_m] = wv.w;
        __syncthreads();
#pragma unroll
        for (int kk = 0; kk < 8; kk++) {
            float ra[8];
            *(float4*)(ra)     = *(const float4*)&As[kk][tm0];
            *(float4*)(ra + 4) = *(const float4*)&As[kk][tm0 + 4];
            unsigned long long w2[4];
            {
                float4 w0 = *(const float4*)&Ws[kk][tn0];
                float4 w1 = *(const float4*)&Ws[kk][tn0 + 4];
                w2[0] = *(unsigned long long*)&w0.x;
                w2[1] = *(unsigned long long*)&w0.z;
                w2[2] = *(unsigned long long*)&w1.x;
                w2[3] = *(unsigned long long*)&w1.z;
            }
#pragma unroll
            for (int i = 0; i < 8; i++) {
                unsigned long long a2 = pack2(ra[i], ra[i]);
#pragma unroll
                for (int j = 0; j < 4; j++) acc2[i][j] = ffma2(a2, w2[j], acc2[i][j]);
            }
        }
    }

    float bj[8];
#pragma unroll
    for (int j = 0; j < 8; j++) bj[j] = bias[n0 + tn0 + j];
#pragma unroll
    for (int i = 0; i < 8; i++) {
        float* cr = &C[(size_t)(m0 + tm0 + i) * N + n0 + tn0];
#pragma unroll
        for (int j = 0; j < 4; j++) {
            float lo, hi;
            unpack2(acc2[i][j], lo, hi);
            cr[2 * j]     = lo + bj[2 * j];
            cr[2 * j + 1] = hi + bj[2 * j + 1];
        }
    }
}

// ---------------- clustered LSTM scan ----------------
// Cluster of 8 CTAs per (dir, batch-group of 8). Each CTA owns 32 hidden units
// (all 4 gates) with its 128KB w_hh slice RESIDENT in SMEM, packed as even/odd-k
// pairs for f32x2 FMA. h exchanged via DSMEM push, double-buffered, one
// cluster barrier per step.
//
// SMEM layout (dynamic, 147456 B):
//   [0, 131072)       : weights, float2 pairs: slot index ((kp*32 + u)*4 + gate)
//                       value = (w[g*256+ug][2kp], w[g*256+ug][2kp+1])
//   [131072, 147456)  : h buffers, float2: [buf:2][kp:128][b:8]
#define SMEM_W_BYTES 131072
#define SMEM_H_OFF   131072
#define SCAN_SMEM    147456

__global__ void __launch_bounds__(256, 1) __cluster_dims__(8, 1, 1)
lstm_scan_cl(const float* __restrict__ xpf,
             const float* __restrict__ xpb,
             const float* __restrict__ whh_f,
             const float* __restrict__ whh_b,
             float* __restrict__ out) {
    extern __shared__ char smem[];
    uint32_t smem_base;
    asm("{ .reg .u64 t; cvta.to.shared.u64 t, %1; cvt.u32.u64 %0, t; }"
        : "=r"(smem_base) : "l"(smem));

    int slice = blockIdx.x;           // 0..7 = cluster rank = unit slice
    int bg    = blockIdx.y;           // 0..3 batch group
    int d     = blockIdx.z;           // 0 fw, 1 bw
    const float* xp = d ? xpb : xpf;
    const float* W  = d ? whh_b : whh_f;

    int tid = threadIdx.x;
    int u  = tid >> 3;                // 0..31 local unit
    int b  = tid & 7;                 // 0..7 local batch
    int ug = slice * 32 + u;          // global unit 0..255
    int bglob = bg * 8 + b;           // global batch

    // ---- load resident weight slice (once) ----
    float2* wsh = (float2*)smem;
    for (int i = tid; i < 128 * 32 * 4; i += 256) {
        int g  = i & 3;
        int uu = (i >> 2) & 31;
        int kp = i >> 7;
        int row = g * 256 + slice * 32 + uu;
        wsh[i] = *(const float2*)&W[(size_t)row * HID + 2 * kp];
    }
    // ---- zero h buffers ----
    float2* hsh = (float2*)(smem + SMEM_H_OFF);
    for (int i = tid; i < 2048; i += 256) hsh[i] = make_float2(0.f, 0.f);
    __syncthreads();

    const unsigned long long* wq = (const unsigned long long*)smem;
    const unsigned long long* hbase = (const unsigned long long*)(smem + SMEM_H_OFF);

    float c = 0.f;
    uint32_t hpush_base = smem_base + SMEM_H_OFF + (uint32_t)(((ug >> 1) * 8 + b) * 8 + (ug & 1) * 4);

    for (int t = 0; t < SEQ; t++) {
        int s = d ? (SEQ - 1 - t) : t;
        const float* xr = xp + ((size_t)bglob * SEQ + s) * G4;
        // issue gate-bias loads early (consumed after k-loop)
        float xi = xr[ug];
        float xf = xr[ug + 256];
        float xg = xr[ug + 512];
        float xo = xr[ug + 768];

        const unsigned long long* hrow = hbase + (size_t)(t & 1) * 1024 + b;
        const unsigned long long* wrow = wq + (size_t)u * 4;

        unsigned long long ai2 = 0ull, af2 = 0ull, ag2 = 0ull, ao2 = 0ull;
#pragma unroll 4
        for (int kp = 0; kp < 128; kp++) {
            unsigned long long h2 = hrow[kp * 8];
            const unsigned long long* wk = wrow + (size_t)kp * 128;
            ai2 = ffma2(h2, wk[0], ai2);
            af2 = ffma2(h2, wk[1], af2);
            ag2 = ffma2(h2, wk[2], ag2);
            ao2 = ffma2(h2, wk[3], ao2);
        }
        float l0, h0v, l1, h1v, l2, h2v, l3, h3v;
        unpack2(ai2, l0, h0v);
        unpack2(af2, l1, h1v);
        unpack2(ag2, l2, h2v);
        unpack2(ao2, l3, h3v);
        float ai = xi + l0 + h0v;
        float af = xf + l1 + h1v;
        float ag = xg + l2 + h2v;
        float ao = xo + l3 + h3v;

        float ig = sigm_fast(ai);
        float fg = sigm_fast(af);
        float gg = tanh_fast(ag);
        float og = sigm_fast(ao);
        c = fg * c + ig * gg;
        float h = og * tanh_fast(c);

        // push h to all 8 CTAs' next-parity buffer
        uint32_t la = hpush_base + (uint32_t)(((t + 1) & 1) * 8192);
#pragma unroll
        for (int cta = 0; cta < 8; cta++) {
            uint32_t ra;
            asm("mapa.shared::cluster.u32 %0, %1, %2;" : "=r"(ra) : "r"(la), "r"(cta));
            asm volatile("st.shared::cluster.f32 [%0], %1;" :: "r"(ra), "f"(h) : "memory");
        }
        out[((size_t)bglob * SEQ + s) * H2 + d * HID + ug] = h;

        asm volatile("barrier.cluster.arrive.aligned;" ::: "memory");
        asm volatile("barrier.cluster.wait.aligned;" ::: "memory");
    }
}

// ---------------- attention scores -> e = exp(s - max_t s) ----------------
__global__ void __launch_bounds__(256) attn_scores(const float* __restrict__ h,
                                                   const float* __restrict__ attn_w,
                                                   const float* __restrict__ attn_b,
                                                   float* __restrict__ e_out) {
    int b = blockIdx.x;
    int tid = threadIdx.x;
    __shared__ float sc[SEQ];
    __shared__ float red[256];
    __shared__ float wsh[H2];
    wsh[tid]       = attn_w[tid];
    wsh[tid + 256] = attn_w[tid + 256];
    __syncthreads();
    float ab = attn_b[0];
    float mx = -1e30f;
    for (int t = tid; t < SEQ; t += 256) {
        const float* hr = h + ((size_t)b * SEQ + t) * H2;
        float acc = 0.f;
#pragma unroll 4
        for (int cch = 0; cch < H2; cch += 4) {
            float4 hv = *(const float4*)&hr[cch];
            acc += hv.x * wsh[cch] + hv.y * wsh[cch + 1] + hv.z * wsh[cch + 2] + hv.w * wsh[cch + 3];
        }
        acc += ab;
        sc[t] = acc;
        mx = fmaxf(mx, acc);
    }
    red[tid] = mx;
    __syncthreads();
    for (int s = 128; s > 0; s >>= 1) {
        if (tid < s) red[tid] = fmaxf(red[tid], red[tid + s]);
        __syncthreads();
    }
    mx = red[0];
    for (int t = tid; t < SEQ; t += 256)
        e_out[b * SEQ + t] = expf(sc[t] - mx);
}

// ---------------- running-softmax context ----------------
__global__ void __launch_bounds__(512) ctx_kernel(const float* __restrict__ h,
                                                  const float* __restrict__ e,
                                                  float* __restrict__ ctx) {
    int b = blockIdx.x;
    int ch = threadIdx.x;
    const float* eb = e + b * SEQ;
    float num = 0.f, den = 0.f;
    for (int t = 0; t < SEQ; t++) {
        float et = eb[t];
        den += et;
        size_t off = ((size_t)b * SEQ + t) * H2 + ch;
        num += et * h[off];
        ctx[off] = num / den;
    }
}

// ---------------- launch ----------------
extern "C" void kernel_launch(void* const* d_in, const int* in_sizes, int n_in,
                              void* d_out, int out_size) {
    const float* x        = (const float*)d_in[0];
    const float* w_ih_l0f = (const float*)d_in[1];
    const float* w_hh_l0f = (const float*)d_in[2];
    const float* b_l0f    = (const float*)d_in[3];
    const float* w_ih_l0b = (const float*)d_in[4];
    const float* w_hh_l0b = (const float*)d_in[5];
    const float* b_l0b    = (const float*)d_in[6];
    const float* w_ih_l1f = (const float*)d_in[7];
    const float* w_hh_l1f = (const float*)d_in[8];
    const float* b_l1f    = (const float*)d_in[9];
    const float* w_ih_l1b = (const float*)d_in[10];
    const float* w_hh_l1b = (const float*)d_in[11];
    const float* b_l1b    = (const float*)d_in[12];
    const float* attn_w   = (const float*)d_in[13];
    const float* attn_b   = (const float*)d_in[14];
    const float* head_w   = (const float*)d_in[15];
    const float* head_b   = (const float*)d_in[16];
    float* out = (float*)d_out;

    float *xpf, *xpb, *h0, *h1, *ctx, *ev;
    cudaGetSymbolAddress((void**)&xpf, g_xpf);
    cudaGetSymbolAddress((void**)&xpb, g_xpb);
    cudaGetSymbolAddress((void**)&h0,  g_h0);
    cudaGetSymbolAddress((void**)&h1,  g_h1);
    cudaGetSymbolAddress((void**)&ctx, g_ctx);
    cudaGetSymbolAddress((void**)&ev,  g_e);

    const int M = BATCH * SEQ;   // 32768

    cudaFuncSetAttribute(lstm_scan_cl, cudaFuncAttributeMaxDynamicSharedMemorySize, SCAN_SMEM);

    // layer 0 input projections: [32768,128] x [1024,128]^T -> [32768,1024]
    {
        dim3 grid(M / 128, G4 / 128);
        sgemm_tn<<<grid, 256>>>(x, w_ih_l0f, b_l0f, xpf, M, G4, DIN);
        sgemm_tn<<<grid, 256>>>(x, w_ih_l0b, b_l0b, xpb, M, G4, DIN);
    }
    // layer 0 scan: grid (slice=8, batchgroup=4, dir=2), cluster (8,1,1)
    {
        dim3 grid(8, 4, 2);
        lstm_scan_cl<<<grid, 256, SCAN_SMEM>>>(xpf, xpb, w_hh_l0f, w_hh_l0b, h0);
    }
    // layer 1 input projections: K=512
    {
        dim3 grid(M / 128, G4 / 128);
        sgemm_tn<<<grid, 256>>>(h0, w_ih_l1f, b_l1f, xpf, M, G4, H2);
        sgemm_tn<<<grid, 256>>>(h0, w_ih_l1b, b_l1b, xpb, M, G4, H2);
    }
    // layer 1 scan
    {
        dim3 grid(8, 4, 2);
        lstm_scan_cl<<<grid, 256, SCAN_SMEM>>>(xpf, xpb, w_hh_l1f, w_hh_l1b, h1);
    }
    // attention + running softmax context
    attn_scores<<<BATCH, 256>>>(h1, attn_w, attn_b, ev);
    ctx_kernel<<<BATCH, 512>>>(h1, ev, ctx);

    // head: [32768,512] x [128,512]^T + head_b -> out [32768,128]
    {
        dim3 grid(M / 128, DIN / 128);
        sgemm_tn<<<grid, 256>>>(ctx, head_w, head_b, out, M, DIN, H2);
    }
}

// round 6
// speedup vs baseline: 1.8328x; 1.1985x over previous
#include <cuda_runtime.h>
#include <math.h>
#include <stdint.h>

#define BATCH 32
#define SEQ   1024
#define DIN   128
#define HID   256
#define G4    1024   // 4*H
#define H2    512    // 2*H

// ---------------- scratch (device globals; no allocation allowed) ----------------
__device__ float  g_xpf[(size_t)BATCH * SEQ * G4];   // 128 MB
__device__ float  g_xpb[(size_t)BATCH * SEQ * G4];   // 128 MB
__device__ float  g_h0 [(size_t)BATCH * SEQ * H2];   // 64 MB
__device__ float  g_h1 [(size_t)BATCH * SEQ * H2];   // 64 MB
__device__ float  g_ctx[(size_t)BATCH * SEQ * H2];   // 64 MB
__device__ float  g_e  [BATCH * SEQ];

// ---------------- helpers ----------------
__device__ __forceinline__ uint32_t smem_u32(const void* p) {
    uint32_t a;
    asm("{ .reg .u64 t; cvta.to.shared.u64 t, %1; cvt.u32.u64 %0, t; }" : "=r"(a) : "l"(p));
    return a;
}
__device__ __forceinline__ uint32_t cvt_tf32(float x) {
    uint32_t r; asm("cvt.rna.tf32.f32 %0, %1;" : "=r"(r) : "f"(x)); return r;
}
__device__ __forceinline__ void mma8(float* d, const uint32_t* a, const uint32_t* b) {
    asm volatile("mma.sync.aligned.m16n8k8.row.col.f32.tf32.tf32.f32 "
        "{%0,%1,%2,%3}, {%4,%5,%6,%7}, {%8,%9}, {%0,%1,%2,%3};"
        : "+f"(d[0]), "+f"(d[1]), "+f"(d[2]), "+f"(d[3])
        : "r"(a[0]), "r"(a[1]), "r"(a[2]), "r"(a[3]), "r"(b[0]), "r"(b[1]));
}

// ---------------- tf32 split-precision GEMM via mma.sync ----------------
// C[m*Nld+n] = bias[n] + sum_k A[m*K+k] * W[n*K+k]
// 128x128 tile / CTA, K-chunks of 32, 256 threads (8 warps, each 64x32).
// SMEM: 2 buffers x { A_hi, A_lo, B_hi, B_lo : 4096 u32 each } = 128KB.
#define BUF_U32   16384
#define GEMM_SMEM (2 * 65536)

__device__ __forceinline__ void g_ldg(const float* __restrict__ A, const float* __restrict__ W,
                                      int m0, int n0, int K, int kbase, int tid,
                                      float4* aR, float4* bR) {
#pragma unroll
    for (int i = 0; i < 4; i++) {
        int lin = tid + i * 256;
        int row = lin >> 3, cg = lin & 7;
        aR[i] = *(const float4*)&A[(size_t)(m0 + row) * K + kbase + cg * 4];
        bR[i] = *(const float4*)&W[(size_t)(n0 + row) * K + kbase + cg * 4];
    }
}

__device__ __forceinline__ void g_stage(uint32_t* buf, const float4* aR, const float4* bR, int tid) {
    uint32_t* Ah = buf;
    uint32_t* Al = buf + 4096;
    uint32_t* Bh = buf + 8192;
    uint32_t* Bl = buf + 12288;
#pragma unroll
    for (int i = 0; i < 4; i++) {
        int lin = tid + i * 256;
        int row = lin >> 3, cg = lin & 7;
        float av[4] = { aR[i].x, aR[i].y, aR[i].z, aR[i].w };
        float wv[4] = { bR[i].x, bR[i].y, bR[i].z, bR[i].w };
#pragma unroll
        for (int j = 0; j < 4; j++) {
            int col = cg * 4 + j;
            int ks = col >> 3, c8 = col & 7, tig = c8 & 3, half = c8 >> 2;
            int lane = ((row & 7) << 2) | tig;
            // A fragment slot
            int regA = ((row >> 3) & 1) | (half << 1);
            int idxA = ((ks * 8 + (row >> 4)) * 32 + lane) * 4 + regA;
            uint32_t hi = cvt_tf32(av[j]);
            uint32_t lo = cvt_tf32(av[j] - __uint_as_float(hi));
            Ah[idxA] = hi; Al[idxA] = lo;
            // B fragment slot (row here is n)
            int idxB = ((ks * 16 + (row >> 3)) * 32 + lane) * 2 + half;
            hi = cvt_tf32(wv[j]);
            lo = cvt_tf32(wv[j] - __uint_as_float(hi));
            Bh[idxB] = hi; Bl[idxB] = lo;
        }
    }
}

__global__ void __launch_bounds__(256, 1) mma_gemm(const float* __restrict__ A,
                                                   const float* __restrict__ W,
                                                   const float* __restrict__ bias,
                                                   float* __restrict__ C,
                                                   int Nld, int K) {
    extern __shared__ uint32_t sm[];
    int tid = threadIdx.x;
    int lane = tid & 31;
    int warp = tid >> 5;
    int wm = warp >> 2, wn = warp & 3;
    int m0 = blockIdx.x * 128, n0 = blockIdx.y * 128;

    float acc[4][4][4];
#pragma unroll
    for (int a = 0; a < 4; a++)
#pragma unroll
        for (int b = 0; b < 4; b++)
#pragma unroll
            for (int c = 0; c < 4; c++) acc[a][b][c] = 0.f;

    float4 aR[4], bR[4];
    g_ldg(A, W, m0, n0, K, 0, tid, aR, bR);
    g_stage(sm, aR, bR, tid);
    __syncthreads();

    const int KT = K / 32;
    for (int kt = 0; kt < KT; kt++) {
        if (kt + 1 < KT) g_ldg(A, W, m0, n0, K, (kt + 1) * 32, tid, aR, bR);

        const uint32_t* buf = sm + (kt & 1) * BUF_U32;
        const uint32_t* Ah = buf;
        const uint32_t* Al = buf + 4096;
        const uint32_t* Bh = buf + 8192;
        const uint32_t* Bl = buf + 12288;
#pragma unroll
        for (int ks = 0; ks < 4; ks++) {
            uint32_t fAh[4][4], fAl[4][4], fBh[4][2], fBl[4][2];
#pragma unroll
            for (int mf = 0; mf < 4; mf++) {
                uint4 v = *(const uint4*)&Ah[((ks * 8 + wm * 4 + mf) * 32 + lane) * 4];
                fAh[mf][0] = v.x; fAh[mf][1] = v.y; fAh[mf][2] = v.z; fAh[mf][3] = v.w;
                uint4 u = *(const uint4*)&Al[((ks * 8 + wm * 4 + mf) * 32 + lane) * 4];
                fAl[mf][0] = u.x; fAl[mf][1] = u.y; fAl[mf][2] = u.z; fAl[mf][3] = u.w;
            }
#pragma unroll
            for (int nf = 0; nf < 4; nf++) {
                uint2 v = *(const uint2*)&Bh[((ks * 16 + wn * 4 + nf) * 32 + lane) * 2];
                fBh[nf][0] = v.x; fBh[nf][1] = v.y;
                uint2 u = *(const uint2*)&Bl[((ks * 16 + wn * 4 + nf) * 32 + lane) * 2];
                fBl[nf][0] = u.x; fBl[nf][1] = u.y;
            }
#pragma unroll
            for (int mf = 0; mf < 4; mf++)
#pragma unroll
                for (int nf = 0; nf < 4; nf++) {
                    mma8(acc[mf][nf], fAh[mf], fBh[nf]);
                    mma8(acc[mf][nf], fAh[mf], fBl[nf]);
                    mma8(acc[mf][nf], fAl[mf], fBh[nf]);
                }
        }
        if (kt + 1 < KT) g_stage(sm + ((kt + 1) & 1) * BUF_U32, aR, bR, tid);
        __syncthreads();
    }

    // epilogue: direct register -> global with bias
    int g = lane >> 2, tig = lane & 3;
#pragma unroll
    for (int mf = 0; mf < 4; mf++) {
#pragma unroll
        for (int nf = 0; nf < 4; nf++) {
            int row = m0 + wm * 64 + mf * 16 + g;
            int col = n0 + wn * 32 + nf * 8 + tig * 2;
            float b0 = bias[col], b1 = bias[col + 1];
            float2 v0 = make_float2(acc[mf][nf][0] + b0, acc[mf][nf][1] + b1);
            float2 v1 = make_float2(acc[mf][nf][2] + b0, acc[mf][nf][3] + b1);
            *(float2*)&C[(size_t)row * Nld + col]       = v0;
            *(float2*)&C[(size_t)(row + 8) * Nld + col] = v1;
        }
    }
}

// ---------------- f32x2 packed-FMA helpers ----------------
__device__ __forceinline__ unsigned long long ffma2(unsigned long long a,
                                                    unsigned long long b,
                                                    unsigned long long c) {
    unsigned long long d;
    asm("fma.rn.f32x2 %0, %1, %2, %3;" : "=l"(d) : "l"(a), "l"(b), "l"(c));
    return d;
}
__device__ __forceinline__ void unpack2(unsigned long long v, float& x, float& y) {
    asm("mov.b64 {%0, %1}, %2;" : "=f"(x), "=f"(y) : "l"(v));
}
__device__ __forceinline__ float sigm_fast(float x) { return 1.f / (1.f + __expf(-x)); }
__device__ __forceinline__ float tanh_fast(float x) { return 2.f / (1.f + __expf(-2.f * x)) - 1.f; }

// ---------------- clustered LSTM scan (now 128 CTAs: 4 batches/CTA, 128 threads) ----------------
// Cluster of 8 CTAs (unit slices) per (dir, batch-group of 4).
// SMEM: [0,131072) resident w_hh slice (float2 even/odd-k pairs),
//       [131072, 139264) h double buffer: float2 [buf:2][kp:128][b:4]
#define SMEM_H_OFF   131072
#define SCAN_SMEM    139264

__global__ void __launch_bounds__(128, 1) __cluster_dims__(8, 1, 1)
lstm_scan_cl(const float* __restrict__ xpf,
             const float* __restrict__ xpb,
             const float* __restrict__ whh_f,
             const float* __restrict__ whh_b,
             float* __restrict__ out) {
    extern __shared__ char smem[];
    uint32_t smem_base = smem_u32(smem);

    int slice = blockIdx.x;           // 0..7 cluster rank = unit slice
    int bg    = blockIdx.y;           // 0..7 batch group (4 batches)
    int d     = blockIdx.z;           // 0 fw, 1 bw
    const float* xp = d ? xpb : xpf;
    const float* W  = d ? whh_b : whh_f;

    int tid = threadIdx.x;
    int u  = tid >> 2;                // 0..31 local unit
    int b  = tid & 3;                 // 0..3 local batch
    int ug = slice * 32 + u;
    int bglob = bg * 4 + b;

    // resident weight slice: slot ((kp*32 + u)*4 + gate) = (w[g*256+ug][2kp], [2kp+1])
    float2* wsh = (float2*)smem;
    for (int i = tid; i < 128 * 32 * 4; i += 128) {
        int g  = i & 3;
        int uu = (i >> 2) & 31;
        int kp = i >> 7;
        int row = g * 256 + slice * 32 + uu;
        wsh[i] = *(const float2*)&W[(size_t)row * HID + 2 * kp];
    }
    float2* hsh = (float2*)(smem + SMEM_H_OFF);
    for (int i = tid; i < 1024; i += 128) hsh[i] = make_float2(0.f, 0.f);
    __syncthreads();

    const unsigned long long* wq = (const unsigned long long*)smem;
    const unsigned long long* hbase = (const unsigned long long*)(smem + SMEM_H_OFF);

    float c = 0.f;
    uint32_t hpush_base = smem_base + SMEM_H_OFF +
                          (uint32_t)(((ug >> 1) * 4 + b) * 8 + (ug & 1) * 4);

    for (int t = 0; t < SEQ; t++) {
        int s = d ? (SEQ - 1 - t) : t;
        const float* xr = xp + ((size_t)bglob * SEQ + s) * G4;
        float xi = xr[ug];
        float xf = xr[ug + 256];
        float xg = xr[ug + 512];
        float xo = xr[ug + 768];

        const unsigned long long* hrow = hbase + (size_t)(t & 1) * 512 + b;
        const unsigned long long* wrow = wq + (size_t)u * 4;

        unsigned long long ai2 = 0ull, af2 = 0ull, ag2 = 0ull, ao2 = 0ull;
#pragma unroll 4
        for (int kp = 0; kp < 128; kp++) {
            unsigned long long h2 = hrow[kp * 4];
            const unsigned long long* wk = wrow + (size_t)kp * 128;
            ai2 = ffma2(h2, wk[0], ai2);
            af2 = ffma2(h2, wk[1], af2);
            ag2 = ffma2(h2, wk[2], ag2);
            ao2 = ffma2(h2, wk[3], ao2);
        }
        float l0, h0v, l1, h1v, l2, h2v, l3, h3v;
        unpack2(ai2, l0, h0v);
        unpack2(af2, l1, h1v);
        unpack2(ag2, l2, h2v);
        unpack2(ao2, l3, h3v);
        float ai = xi + l0 + h0v;
        float af = xf + l1 + h1v;
        float ag = xg + l2 + h2v;
        float ao = xo + l3 + h3v;

        float ig = sigm_fast(ai);
        float fg = sigm_fast(af);
        float gg = tanh_fast(ag);
        float og = sigm_fast(ao);
        c = fg * c + ig * gg;
        float h = og * tanh_fast(c);

        uint32_t la = hpush_base + (uint32_t)(((t + 1) & 1) * 4096);
#pragma unroll
        for (int cta = 0; cta < 8; cta++) {
            uint32_t ra;
            asm("mapa.shared::cluster.u32 %0, %1, %2;" : "=r"(ra) : "r"(la), "r"(cta));
            asm volatile("st.shared::cluster.f32 [%0], %1;" :: "r"(ra), "f"(h) : "memory");
        }
        out[((size_t)bglob * SEQ + s) * H2 + d * HID + ug] = h;

        asm volatile("barrier.cluster.arrive.aligned;" ::: "memory");
        asm volatile("barrier.cluster.wait.aligned;" ::: "memory");
    }
}

// ---------------- attention scores -> e = exp(s - max_t s) ----------------
__global__ void __launch_bounds__(256) attn_scores(const float* __restrict__ h,
                                                   const float* __restrict__ attn_w,
                                                   const float* __restrict__ attn_b,
                                                   float* __restrict__ e_out) {
    int b = blockIdx.x;
    int tid = threadIdx.x;
    __shared__ float sc[SEQ];
    __shared__ float red[256];
    __shared__ float wsh[H2];
    wsh[tid]       = attn_w[tid];
    wsh[tid + 256] = attn_w[tid + 256];
    __syncthreads();
    float ab = attn_b[0];
    float mx = -1e30f;
    for (int t = tid; t < SEQ; t += 256) {
        const float* hr = h + ((size_t)b * SEQ + t) * H2;
        float acc = 0.f;
#pragma unroll 4
        for (int cch = 0; cch < H2; cch += 4) {
            float4 hv = *(const float4*)&hr[cch];
            acc += hv.x * wsh[cch] + hv.y * wsh[cch + 1] + hv.z * wsh[cch + 2] + hv.w * wsh[cch + 3];
        }
        acc += ab;
        sc[t] = acc;
        mx = fmaxf(mx, acc);
    }
    red[tid] = mx;
    __syncthreads();
    for (int s = 128; s > 0; s >>= 1) {
        if (tid < s) red[tid] = fmaxf(red[tid], red[tid + s]);
        __syncthreads();
    }
    mx = red[0];
    for (int t = tid; t < SEQ; t += 256)
        e_out[b * SEQ + t] = expf(sc[t] - mx);
}

// ---------------- running-softmax context ----------------
__global__ void __launch_bounds__(512) ctx_kernel(const float* __restrict__ h,
                                                  const float* __restrict__ e,
                                                  float* __restrict__ ctx) {
    int b = blockIdx.x;
    int ch = threadIdx.x;
    const float* eb = e + b * SEQ;
    float num = 0.f, den = 0.f;
    for (int t = 0; t < SEQ; t++) {
        float et = eb[t];
        den += et;
        size_t off = ((size_t)b * SEQ + t) * H2 + ch;
        num += et * h[off];
        ctx[off] = num / den;
    }
}

// ---------------- launch ----------------
extern "C" void kernel_launch(void* const* d_in, const int* in_sizes, int n_in,
                              void* d_out, int out_size) {
    const float* x        = (const float*)d_in[0];
    const float* w_ih_l0f = (const float*)d_in[1];
    const float* w_hh_l0f = (const float*)d_in[2];
    const float* b_l0f    = (const float*)d_in[3];
    const float* w_ih_l0b = (const float*)d_in[4];
    const float* w_hh_l0b = (const float*)d_in[5];
    const float* b_l0b    = (const float*)d_in[6];
    const float* w_ih_l1f = (const float*)d_in[7];
    const float* w_hh_l1f = (const float*)d_in[8];
    const float* b_l1f    = (const float*)d_in[9];
    const float* w_ih_l1b = (const float*)d_in[10];
    const float* w_hh_l1b = (const float*)d_in[11];
    const float* b_l1b    = (const float*)d_in[12];
    const float* attn_w   = (const float*)d_in[13];
    const float* attn_b   = (const float*)d_in[14];
    const float* head_w   = (const float*)d_in[15];
    const float* head_b   = (const float*)d_in[16];
    float* out = (float*)d_out;

    float *xpf, *xpb, *h0, *h1, *ctx, *ev;
    cudaGetSymbolAddress((void**)&xpf, g_xpf);
    cudaGetSymbolAddress((void**)&xpb, g_xpb);
    cudaGetSymbolAddress((void**)&h0,  g_h0);
    cudaGetSymbolAddress((void**)&h1,  g_h1);
    cudaGetSymbolAddress((void**)&ctx, g_ctx);
    cudaGetSymbolAddress((void**)&ev,  g_e);

    const int M = BATCH * SEQ;   // 32768

    cudaFuncSetAttribute(lstm_scan_cl, cudaFuncAttributeMaxDynamicSharedMemorySize, SCAN_SMEM);
    cudaFuncSetAttribute(mma_gemm,     cudaFuncAttributeMaxDynamicSharedMemorySize, GEMM_SMEM);

    // layer 0 input projections: [32768,128] x [1024,128]^T -> [32768,1024]
    {
        dim3 grid(M / 128, G4 / 128);
        mma_gemm<<<grid, 256, GEMM_SMEM>>>(x, w_ih_l0f, b_l0f, xpf, G4, DIN);
        mma_gemm<<<grid, 256, GEMM_SMEM>>>(x, w_ih_l0b, b_l0b, xpb, G4, DIN);
    }
    // layer 0 scan: grid (slice=8, batchgroup=8, dir=2), cluster (8,1,1)
    {
        dim3 grid(8, 8, 2);
        lstm_scan_cl<<<grid, 128, SCAN_SMEM>>>(xpf, xpb, w_hh_l0f, w_hh_l0b, h0);
    }
    // layer 1 input projections: K=512
    {
        dim3 grid(M / 128, G4 / 128);
        mma_gemm<<<grid, 256, GEMM_SMEM>>>(h0, w_ih_l1f, b_l1f, xpf, G4, H2);
        mma_gemm<<<grid, 256, GEMM_SMEM>>>(h0, w_ih_l1b, b_l1b, xpb, G4, H2);
    }
    // layer 1 scan
    {
        dim3 grid(8, 8, 2);
        lstm_scan_cl<<<grid, 128, SCAN_SMEM>>>(xpf, xpb, w_hh_l1f, w_hh_l1b, h1);
    }
    // attention + running softmax context
    attn_scores<<<BATCH, 256>>>(h1, attn_w, attn_b, ev);
    ctx_kernel<<<BATCH, 512>>>(h1, ev, ctx);

    // head: [32768,512] x [128,512]^T + head_b -> out [32768,128]
    {
        dim3 grid(M / 128, DIN / 128);
        mma_gemm<<<grid, 256, GEMM_SMEM>>>(ctx, head_w, head_b, out, DIN, H2);
    }
}